// round 1
// baseline (speedup 1.0000x reference)
#include <cuda_runtime.h>
#include <math.h>

#define BB 8
#define SS 2048
#define HH 16
#define HD 64
#define DD 1024
#define MM (BB*SS)          /* 16384 rows */
#define NB 33               /* rfft bins for length-64 */
#define NROW (MM*HH)        /* 262144 (b,s,h) rows */
#define CH 16               /* scan chunks per sequence */
#define CLEN (SS/CH)        /* 128 steps per chunk */

// ---------------- scratch (static device memory; no allocs) ----------------
__device__ float  g_qkv[3][(size_t)MM*DD];                 // q,k,v projections (201 MB)
__device__ float2 g_w  [(size_t)BB*HH*SS*NB];              // bind spectra (69 MB)
__device__ float2 g_qc [(size_t)BB*HH*SS*NB];              // conj(q_hat) (69 MB)
__device__ float2 g_cs [(size_t)BB*HH*CH*NB];              // chunk partial sums

// ---------------------------------------------------------------------------
// Kernel 1: fp32 SGEMM, C = X @ W + bias, for q/k/v selected by blockIdx.z.
// 128x128 block tile, 8x8 per-thread microtile, K-step 8, reg prefetch.
// ---------------------------------------------------------------------------
__global__ __launch_bounds__(256, 2)
void sgemm_qkv_kernel(const float* __restrict__ X,
                      const float* __restrict__ W0, const float* __restrict__ b0,
                      const float* __restrict__ W1, const float* __restrict__ b1,
                      const float* __restrict__ W2, const float* __restrict__ b2)
{
    const int which = blockIdx.z;
    const float* Wm   = (which == 0) ? W0 : (which == 1) ? W1 : W2;
    const float* bias = (which == 0) ? b0 : (which == 1) ? b1 : b2;
    float* C = &g_qkv[which][0];

    __shared__ float As[8][128];
    __shared__ float Bs[8][128];

    const int t  = threadIdx.x;
    const int tx = t & 15;
    const int ty = t >> 4;

    const int aRow = t >> 1;          // 0..127
    const int aCol = (t & 1) << 2;    // 0 or 4
    const int bRow = t >> 5;          // 0..7
    const int bCol = (t & 31) << 2;   // 0..124

    const float* Ap = X  + (size_t)(blockIdx.y * 128 + aRow) * DD + aCol;
    const float* Bp = Wm + (size_t)bRow * DD + blockIdx.x * 128 + bCol;

    float acc[8][8];
#pragma unroll
    for (int i = 0; i < 8; i++)
#pragma unroll
        for (int j = 0; j < 8; j++) acc[i][j] = 0.f;

    float4 a4 = *(const float4*)Ap;
    float4 b4 = *(const float4*)Bp;

    for (int kt = 0; kt < DD / 8; kt++) {
        As[aCol + 0][aRow] = a4.x;
        As[aCol + 1][aRow] = a4.y;
        As[aCol + 2][aRow] = a4.z;
        As[aCol + 3][aRow] = a4.w;
        *(float4*)&Bs[bRow][bCol] = b4;
        __syncthreads();

        if (kt < DD / 8 - 1) {
            a4 = *(const float4*)(Ap + (size_t)(kt + 1) * 8);
            b4 = *(const float4*)(Bp + (size_t)(kt + 1) * 8 * DD);
        }

#pragma unroll
        for (int k = 0; k < 8; k++) {
            float rm[8], rn[8];
            *(float4*)&rm[0] = *(const float4*)&As[k][ty * 8];
            *(float4*)&rm[4] = *(const float4*)&As[k][ty * 8 + 4];
            *(float4*)&rn[0] = *(const float4*)&Bs[k][tx * 8];
            *(float4*)&rn[4] = *(const float4*)&Bs[k][tx * 8 + 4];
#pragma unroll
            for (int i = 0; i < 8; i++)
#pragma unroll
                for (int j = 0; j < 8; j++)
                    acc[i][j] = fmaf(rm[i], rn[j], acc[i][j]);
        }
        __syncthreads();
    }

    const int rowC = blockIdx.y * 128 + ty * 8;
    const int colC = blockIdx.x * 128 + tx * 8;
#pragma unroll
    for (int i = 0; i < 8; i++) {
#pragma unroll
        for (int j = 0; j < 8; j += 4) {
            float4 r;
            r.x = acc[i][j + 0] + bias[colC + j + 0];
            r.y = acc[i][j + 1] + bias[colC + j + 1];
            r.z = acc[i][j + 2] + bias[colC + j + 2];
            r.w = acc[i][j + 3] + bias[colC + j + 3];
            *(float4*)&C[(size_t)(rowC + i) * DD + colC + j] = r;
        }
    }
}

// ---------------------------------------------------------------------------
// Kernel 2: per (b,s,h) row — forward DFT64 of q,k,v (bins 0..32), unit
// projection in freq domain, w = k_hat*v_hat, qc = conj(q_hat). 2 rows/block.
// ---------------------------------------------------------------------------
__global__ __launch_bounds__(128)
void freq_kernel()
{
    __shared__ float sh[2][3][64];
    const int tid  = threadIdx.x;
    const int lr   = tid >> 6;        // local row 0/1
    const int lane = tid & 63;
    const int row  = blockIdx.x * 2 + lr;   // (b*S + s)*H + h

#pragma unroll
    for (int a = 0; a < 3; a++)
        sh[lr][a][lane] = g_qkv[a][(size_t)row * HD + lane];
    __syncthreads();

    if (lane < NB) {
        // phasor step e^{-i 2*pi*lane/64}
        float sc, ss;
        sincosf(6.2831853071795864f * (float)lane / 64.f, &ss, &sc);
        const float cs = sc, sn = -ss;

        float wr = 1.f, wi = 0.f;
        float qr = 0, qi = 0, kr = 0, ki = 0, vr = 0, vi = 0;
#pragma unroll
        for (int n = 0; n < 64; n++) {
            const float xq = sh[lr][0][n];
            const float xk = sh[lr][1][n];
            const float xv = sh[lr][2][n];
            qr = fmaf(xq, wr, qr); qi = fmaf(xq, wi, qi);
            kr = fmaf(xk, wr, kr); ki = fmaf(xk, wi, ki);
            vr = fmaf(xv, wr, vr); vi = fmaf(xv, wi, vi);
            const float nwr = wr * cs - wi * sn;
            const float nwi = wr * sn + wi * cs;
            wr = nwr; wi = nwi;
        }
        // unit projection: f / (|f| + 1e-8)
        const float iq = 1.f / (sqrtf(qr * qr + qi * qi) + 1e-8f);
        const float ik = 1.f / (sqrtf(kr * kr + ki * ki) + 1e-8f);
        const float iv = 1.f / (sqrtf(vr * vr + vi * vi) + 1e-8f);
        qr *= iq; qi *= iq;
        kr *= ik; ki *= ik;
        vr *= iv; vi *= iv;

        const float2 w  = make_float2(kr * vr - ki * vi, kr * vi + ki * vr);
        const float2 qc = make_float2(qr, -qi);

        const int h = row & 15;
        const int m = row >> 4;
        const int s = m & (SS - 1);
        const int b = m >> 11;
        const size_t idx = ((size_t)(b * HH + h) * SS + s) * NB + lane;
        g_w[idx]  = w;
        g_qc[idx] = qc;
    }
}

// ---------------------------------------------------------------------------
// Kernel 3a: per-chunk partial sums of w (for the parallel scan)
// ---------------------------------------------------------------------------
__global__ __launch_bounds__(64)
void chunk_sum_kernel()
{
    const int bh = blockIdx.x;
    const int c  = blockIdx.y;
    const int j  = threadIdx.x;
    if (j >= NB) return;

    size_t base = ((size_t)bh * SS + (size_t)c * CLEN) * NB + j;
    float sx = 0.f, sy = 0.f;
#pragma unroll 4
    for (int s = 0; s < CLEN; s++) {
        const float2 w = g_w[base + (size_t)s * NB];
        sx += w.x; sy += w.y;
    }
    g_cs[((size_t)bh * CH + c) * NB + j] = make_float2(sx, sy);
}

// ---------------------------------------------------------------------------
// Kernel 3b: exclusive scan over the 16 chunk totals per (b,h,bin)
// ---------------------------------------------------------------------------
__global__ __launch_bounds__(64)
void chunk_scan_kernel()
{
    const int bh = blockIdx.x;
    const int j  = threadIdx.x;
    if (j >= NB) return;

    float rx = 0.f, ry = 0.f;
#pragma unroll
    for (int c = 0; c < CH; c++) {
        const size_t idx = ((size_t)bh * CH + c) * NB + j;
        const float2 t = g_cs[idx];
        g_cs[idx] = make_float2(rx, ry);
        rx += t.x; ry += t.y;
    }
}

// ---------------------------------------------------------------------------
// Kernel 3c: within-chunk running sum, multiply by conj(q_hat), fused real
// IDFT64, store output. One block per (b,h,chunk). 64 threads: lanes 0..32
// own bins; all 64 lanes produce one output sample each.
// ---------------------------------------------------------------------------
__global__ __launch_bounds__(64)
void scan_idft_kernel(float* __restrict__ out)
{
    __shared__ float2 of[NB];
    const int bh = blockIdx.x;
    const int c  = blockIdx.y;
    const int n  = threadIdx.x;          // 0..63
    const int b  = bh >> 4;
    const int h  = bh & 15;

    float ax = 0.f, ay = 0.f;
    if (n < NB) {
        const float2 o = g_cs[((size_t)bh * CH + c) * NB + n];
        ax = o.x; ay = o.y;
    }
    const size_t base = ((size_t)bh * SS + (size_t)c * CLEN) * NB;

    // IDFT twiddle step for output sample n: e^{+i 2*pi*n/64}
    float stc, sts;
    sincosf(6.2831853071795864f * (float)n / 64.f, &sts, &stc);

    float2 w  = make_float2(0.f, 0.f), qc = make_float2(0.f, 0.f);
    if (n < NB) { w = g_w[base + n]; qc = g_qc[base + n]; }

    for (int sl = 0; sl < CLEN; sl++) {
        float2 wn = make_float2(0.f, 0.f), qn = make_float2(0.f, 0.f);
        if (n < NB && sl + 1 < CLEN) {               // prefetch next step
            wn = g_w [base + (size_t)(sl + 1) * NB + n];
            qn = g_qc[base + (size_t)(sl + 1) * NB + n];
        }
        if (n < NB) {
            ax += w.x; ay += w.y;                    // running sum S_j
            of[n] = make_float2(ax * qc.x - ay * qc.y,   // S_j * conj(q_hat)
                                ax * qc.y + ay * qc.x);
        }
        __syncthreads();

        // real IDFT64 using conjugate symmetry (bins 0 and 32 are real)
        const float f0   = of[0].x;
        const float f32v = of[32].x;
        float cr = stc, ci = sts;
        float sum = 0.f;
#pragma unroll
        for (int j = 1; j < 32; j++) {
            sum = fmaf(of[j].x, cr, sum);
            sum = fmaf(-of[j].y, ci, sum);
            const float ncr = cr * stc - ci * sts;
            const float nci = cr * sts + ci * stc;
            cr = ncr; ci = nci;
        }
        const int s = c * CLEN + sl;
        const float outv = (f0 + ((n & 1) ? -f32v : f32v) + 2.f * sum) * (1.f / 64.f);
        out[(size_t)(b * SS + s) * DD + h * HD + n] = outv;
        __syncthreads();

        w = wn; qc = qn;
    }
}

// ---------------------------------------------------------------------------
extern "C" void kernel_launch(void* const* d_in, const int* in_sizes, int n_in,
                              void* d_out, int out_size)
{
    const float* x  = (const float*)d_in[0];
    const float* Wq = (const float*)d_in[1];
    const float* bq = (const float*)d_in[2];
    const float* Wk = (const float*)d_in[3];
    const float* bk = (const float*)d_in[4];
    const float* Wv = (const float*)d_in[5];
    const float* bv = (const float*)d_in[6];
    float* out = (float*)d_out;

    dim3 gGemm(DD / 128, MM / 128, 3);
    sgemm_qkv_kernel<<<gGemm, 256>>>(x, Wq, bq, Wk, bk, Wv, bv);

    freq_kernel<<<NROW / 2, 128>>>();

    chunk_sum_kernel<<<dim3(BB * HH, CH), 64>>>();
    chunk_scan_kernel<<<BB * HH, 64>>>();
    scan_idft_kernel<<<dim3(BB * HH, CH), 64>>>(out);
}

// round 3
// speedup vs baseline: 1.8818x; 1.8818x over previous
#include <cuda_runtime.h>
#include <cuda_bf16.h>
#include <math.h>
#include <stdint.h>

#define BB 8
#define SS 2048
#define HH 16
#define HD 64
#define DD 1024
#define MM (BB*SS)          /* 16384 rows */
#define NB 33               /* rfft bins for length-64 */
#define NROW (MM*HH)        /* 262144 (b,s,h) rows */
#define CH 16               /* scan chunks per sequence */
#define CLEN (SS/CH)        /* 128 steps per chunk */

#define KC 32               /* K-chunk per SMEM stage */
#define NKT (DD/KC)         /* 32 stages */
#define STAGE_BYTES 32768   /* A 16KB + B 16KB (hi|lo packed in 128B rows) */
#define DSMEM_BYTES (2*STAGE_BYTES + 128)

// ---------------- scratch (static device memory; no allocs) ----------------
__device__ float  g_qkv[3][(size_t)MM*DD];                 // q,k,v projections
__device__ float2 g_w  [(size_t)BB*HH*SS*NB];              // bind spectra
__device__ float2 g_qc [(size_t)BB*HH*SS*NB];              // conj(q_hat)
__device__ float2 g_cs [(size_t)BB*HH*CH*NB];              // chunk partial sums
__device__ __nv_bfloat16 g_xhi[(size_t)MM*DD];             // X split hi
__device__ __nv_bfloat16 g_xlo[(size_t)MM*DD];             // X split lo
__device__ __nv_bfloat16 g_wthi[3][(size_t)DD*DD];         // W^T split hi [N][K]
__device__ __nv_bfloat16 g_wtlo[3][(size_t)DD*DD];         // W^T split lo [N][K]

// ------------------------------ PTX helpers -------------------------------
__device__ __forceinline__ uint32_t smem_u32(const void* p) {
    uint32_t a;
    asm("{ .reg .u64 t; cvta.to.shared.u64 t, %1; cvt.u32.u64 %0, t; }"
        : "=r"(a) : "l"(p));
    return a;
}
__device__ __forceinline__ void cp16(uint32_t dst, const void* src) {
    asm volatile("cp.async.cg.shared.global [%0], [%1], 16;"
                 :: "r"(dst), "l"(src) : "memory");
}
__device__ __forceinline__ void cp_commit() {
    asm volatile("cp.async.commit_group;" ::: "memory");
}
__device__ __forceinline__ void cp_wait1() {
    asm volatile("cp.async.wait_group 1;" ::: "memory");
}
__device__ __forceinline__ void cp_wait0() {
    asm volatile("cp.async.wait_group 0;" ::: "memory");
}
__device__ __forceinline__ void ldsm4(uint32_t& r0, uint32_t& r1, uint32_t& r2,
                                      uint32_t& r3, uint32_t addr) {
    asm volatile("ldmatrix.sync.aligned.m8n8.x4.shared.b16 {%0,%1,%2,%3}, [%4];"
                 : "=r"(r0), "=r"(r1), "=r"(r2), "=r"(r3) : "r"(addr));
}
__device__ __forceinline__ void mma_bf16(float* c, const uint32_t* a, const uint32_t* b) {
    asm volatile("mma.sync.aligned.m16n8k16.row.col.f32.bf16.bf16.f32 "
                 "{%0,%1,%2,%3},{%4,%5,%6,%7},{%8,%9},{%0,%1,%2,%3};"
                 : "+f"(c[0]), "+f"(c[1]), "+f"(c[2]), "+f"(c[3])
                 : "r"(a[0]), "r"(a[1]), "r"(a[2]), "r"(a[3]),
                   "r"(b[0]), "r"(b[1]));
}

// ---------------------------------------------------------------------------
// Convert X (fp32) -> bf16 hi/lo pair
// ---------------------------------------------------------------------------
__global__ __launch_bounds__(256)
void convert_x_kernel(const float* __restrict__ X)
{
    const size_t total = (size_t)MM * DD / 4;
    for (size_t i = blockIdx.x * 256 + threadIdx.x; i < total; i += (size_t)gridDim.x * 256) {
        float4 f = ((const float4*)X)[i];
        __nv_bfloat16 h0 = __float2bfloat16(f.x);
        __nv_bfloat16 h1 = __float2bfloat16(f.y);
        __nv_bfloat16 h2 = __float2bfloat16(f.z);
        __nv_bfloat16 h3 = __float2bfloat16(f.w);
        __nv_bfloat16 l0 = __float2bfloat16(f.x - __bfloat162float(h0));
        __nv_bfloat16 l1 = __float2bfloat16(f.y - __bfloat162float(h1));
        __nv_bfloat16 l2 = __float2bfloat16(f.z - __bfloat162float(h2));
        __nv_bfloat16 l3 = __float2bfloat16(f.w - __bfloat162float(h3));
        ((__nv_bfloat162*)g_xhi)[i * 2 + 0] = __nv_bfloat162(h0, h1);
        ((__nv_bfloat162*)g_xhi)[i * 2 + 1] = __nv_bfloat162(h2, h3);
        ((__nv_bfloat162*)g_xlo)[i * 2 + 0] = __nv_bfloat162(l0, l1);
        ((__nv_bfloat162*)g_xlo)[i * 2 + 1] = __nv_bfloat162(l2, l3);
    }
}

// ---------------------------------------------------------------------------
// Convert + transpose W (fp32 [K,N]) -> W^T bf16 hi/lo ([N,K])
// ---------------------------------------------------------------------------
__global__ __launch_bounds__(256)
void convert_w_kernel(const float* __restrict__ Wq,
                      const float* __restrict__ Wk,
                      const float* __restrict__ Wv)
{
    __shared__ float tile[32][33];
    const int which = blockIdx.z;
    const float* W = (which == 0) ? Wq : (which == 1) ? Wk : Wv;
    const int n0 = blockIdx.x * 32;
    const int k0 = blockIdx.y * 32;
    const int tx = threadIdx.x, ty = threadIdx.y;

    for (int r = ty; r < 32; r += 8)
        tile[r][tx] = W[(size_t)(k0 + r) * DD + n0 + tx];
    __syncthreads();
    for (int r = ty; r < 32; r += 8) {
        const float f = tile[tx][r];
        const __nv_bfloat16 h = __float2bfloat16(f);
        const __nv_bfloat16 l = __float2bfloat16(f - __bfloat162float(h));
        const size_t o = (size_t)(n0 + r) * DD + k0 + tx;
        g_wthi[which][o] = h;
        g_wtlo[which][o] = l;
    }
}

// ---------------------------------------------------------------------------
// Split-bf16 HMMA GEMM: C[which] = X @ W[which] + bias
// CTA 128x128, 8 warps (2m x 4n), warp tile 64x32, mma.sync m16n8k16 bf16,
// 2-stage cp.async ring. SMEM rows = 128B: [hi k0..31 | lo k0..31] per row,
// SW128 XOR swizzle -> conflict-free ldmatrix.
// ---------------------------------------------------------------------------
__device__ __forceinline__ void copy_stage(uint32_t sA, uint32_t sB, int which,
                                           int rowB, int colB, int kt, int tid)
{
#pragma unroll
    for (int i = 0; i < 4; i++) {
        const int id = tid + i * 256;
        const int r = id >> 3, c = id & 7;
        const __nv_bfloat16* g = (c < 4) ? g_xhi : g_xlo;
        const void* src = g + (size_t)(rowB + r) * DD + kt * KC + (c & 3) * 8;
        cp16(sA + r * 128 + ((c ^ (r & 7)) << 4), src);
    }
#pragma unroll
    for (int i = 0; i < 4; i++) {
        const int id = tid + i * 256;
        const int r = id >> 3, c = id & 7;
        const __nv_bfloat16* g = (c < 4) ? g_wthi[which] : g_wtlo[which];
        const void* src = g + (size_t)(colB + r) * DD + kt * KC + (c & 3) * 8;
        cp16(sB + r * 128 + ((c ^ (r & 7)) << 4), src);
    }
}

__global__ __launch_bounds__(256, 1)
void mma_gemm_kernel(const float* __restrict__ bq,
                     const float* __restrict__ bk,
                     const float* __restrict__ bv)
{
    extern __shared__ __align__(16) char dsm[];
    const int tid = threadIdx.x;
    const int wid = tid >> 5, lane = tid & 31;
    const int wm = wid & 1, wn = wid >> 1;
    const int which = blockIdx.z;
    const int rowB = blockIdx.y * 128;
    const int colB = blockIdx.x * 128;
    const float* bias = (which == 0) ? bq : (which == 1) ? bk : bv;

    uint32_t sbase = smem_u32(dsm);
    sbase = (sbase + 127u) & ~127u;

    float C[4][4][4];
#pragma unroll
    for (int mt = 0; mt < 4; mt++)
#pragma unroll
        for (int nt = 0; nt < 4; nt++)
#pragma unroll
            for (int j = 0; j < 4; j++) C[mt][nt][j] = 0.f;

    copy_stage(sbase, sbase + 16384, which, rowB, colB, 0, tid);
    cp_commit();
    copy_stage(sbase + STAGE_BYTES, sbase + STAGE_BYTES + 16384, which, rowB, colB, 1, tid);
    cp_commit();

    for (int kt = 0; kt < NKT; kt++) {
        cp_wait1();
        __syncthreads();
        const uint32_t sA = sbase + (kt & 1) * STAGE_BYTES;
        const uint32_t sB = sA + 16384;

#pragma unroll
        for (int ks = 0; ks < 2; ks++) {
            uint32_t a[2][4][4];
            uint32_t b[2][4][2];
#pragma unroll
            for (int h = 0; h < 2; h++)
#pragma unroll
                for (int mt = 0; mt < 4; mt++) {
                    const int row = wm * 64 + mt * 16 + (lane & 15);
                    const int c = 2 * ks + (lane >> 4) + h * 4;
                    ldsm4(a[h][mt][0], a[h][mt][1], a[h][mt][2], a[h][mt][3],
                          sA + row * 128 + ((c ^ (row & 7)) << 4));
                }
#pragma unroll
            for (int h = 0; h < 2; h++)
#pragma unroll
                for (int p = 0; p < 2; p++) {
                    const int row = wn * 32 + p * 16 + ((lane >> 4) << 3) + (lane & 7);
                    const int c = 2 * ks + ((lane >> 3) & 1) + h * 4;
                    ldsm4(b[h][2 * p][0], b[h][2 * p][1],
                          b[h][2 * p + 1][0], b[h][2 * p + 1][1],
                          sB + row * 128 + ((c ^ (row & 7)) << 4));
                }
#pragma unroll
            for (int mt = 0; mt < 4; mt++)
#pragma unroll
                for (int nt = 0; nt < 4; nt++) {
                    mma_bf16(C[mt][nt], a[0][mt], b[0][nt]);  // hi*hi
                    mma_bf16(C[mt][nt], a[0][mt], b[1][nt]);  // hi*lo
                    mma_bf16(C[mt][nt], a[1][mt], b[0][nt]);  // lo*hi
                }
        }
        __syncthreads();
        if (kt + 2 < NKT) {
            const uint32_t dA = sbase + (kt & 1) * STAGE_BYTES;
            copy_stage(dA, dA + 16384, which, rowB, colB, kt + 2, tid);
            cp_commit();
        }
    }
    cp_wait0();

    // Epilogue: direct fp32 stores + bias
    float* Cg = &g_qkv[which][0];
    const int rw = rowB + wm * 64;
    const int cw = colB + wn * 32;
#pragma unroll
    for (int mt = 0; mt < 4; mt++) {
#pragma unroll
        for (int nt = 0; nt < 4; nt++) {
            const int r0 = rw + mt * 16 + (lane >> 2);
            const int col = cw + nt * 8 + (lane & 3) * 2;
            const float bx = bias[col], by = bias[col + 1];
            float2 o0 = make_float2(C[mt][nt][0] + bx, C[mt][nt][1] + by);
            float2 o1 = make_float2(C[mt][nt][2] + bx, C[mt][nt][3] + by);
            *(float2*)&Cg[(size_t)r0 * DD + col]       = o0;
            *(float2*)&Cg[(size_t)(r0 + 8) * DD + col] = o1;
        }
    }
}

// ---------------------------------------------------------------------------
// Kernel 2: per (b,s,h) row — forward DFT64 of q,k,v, unit projection in
// freq domain, w = k_hat*v_hat, qc = conj(q_hat). 2 rows/block.
// ---------------------------------------------------------------------------
__global__ __launch_bounds__(128)
void freq_kernel()
{
    __shared__ float sh[2][3][64];
    const int tid  = threadIdx.x;
    const int lr   = tid >> 6;
    const int lane = tid & 63;
    const int row  = blockIdx.x * 2 + lr;

#pragma unroll
    for (int a = 0; a < 3; a++)
        sh[lr][a][lane] = g_qkv[a][(size_t)row * HD + lane];
    __syncthreads();

    if (lane < NB) {
        float sc, ss;
        sincosf(6.2831853071795864f * (float)lane / 64.f, &ss, &sc);
        const float cs = sc, sn = -ss;

        float wr = 1.f, wi = 0.f;
        float qr = 0, qi = 0, kr = 0, ki = 0, vr = 0, vi = 0;
#pragma unroll
        for (int n = 0; n < 64; n++) {
            const float xq = sh[lr][0][n];
            const float xk = sh[lr][1][n];
            const float xv = sh[lr][2][n];
            qr = fmaf(xq, wr, qr); qi = fmaf(xq, wi, qi);
            kr = fmaf(xk, wr, kr); ki = fmaf(xk, wi, ki);
            vr = fmaf(xv, wr, vr); vi = fmaf(xv, wi, vi);
            const float nwr = wr * cs - wi * sn;
            const float nwi = wr * sn + wi * cs;
            wr = nwr; wi = nwi;
        }
        const float iq = 1.f / (sqrtf(qr * qr + qi * qi) + 1e-8f);
        const float ik = 1.f / (sqrtf(kr * kr + ki * ki) + 1e-8f);
        const float iv = 1.f / (sqrtf(vr * vr + vi * vi) + 1e-8f);
        qr *= iq; qi *= iq;
        kr *= ik; ki *= ik;
        vr *= iv; vi *= iv;

        const float2 w  = make_float2(kr * vr - ki * vi, kr * vi + ki * vr);
        const float2 qc = make_float2(qr, -qi);

        const int h = row & 15;
        const int m = row >> 4;
        const int s = m & (SS - 1);
        const int b = m >> 11;
        const size_t idx = ((size_t)(b * HH + h) * SS + s) * NB + lane;
        g_w[idx]  = w;
        g_qc[idx] = qc;
    }
}

// ---------------------------------------------------------------------------
__global__ __launch_bounds__(64)
void chunk_sum_kernel()
{
    const int bh = blockIdx.x;
    const int c  = blockIdx.y;
    const int j  = threadIdx.x;
    if (j >= NB) return;

    size_t base = ((size_t)bh * SS + (size_t)c * CLEN) * NB + j;
    float sx = 0.f, sy = 0.f;
#pragma unroll 4
    for (int s = 0; s < CLEN; s++) {
        const float2 w = g_w[base + (size_t)s * NB];
        sx += w.x; sy += w.y;
    }
    g_cs[((size_t)bh * CH + c) * NB + j] = make_float2(sx, sy);
}

__global__ __launch_bounds__(64)
void chunk_scan_kernel()
{
    const int bh = blockIdx.x;
    const int j  = threadIdx.x;
    if (j >= NB) return;

    float rx = 0.f, ry = 0.f;
#pragma unroll
    for (int c = 0; c < CH; c++) {
        const size_t idx = ((size_t)bh * CH + c) * NB + j;
        const float2 t = g_cs[idx];
        g_cs[idx] = make_float2(rx, ry);
        rx += t.x; ry += t.y;
    }
}

__global__ __launch_bounds__(64)
void scan_idft_kernel(float* __restrict__ out)
{
    __shared__ float2 of[NB];
    const int bh = blockIdx.x;
    const int c  = blockIdx.y;
    const int n  = threadIdx.x;
    const int b  = bh >> 4;
    const int h  = bh & 15;

    float ax = 0.f, ay = 0.f;
    if (n < NB) {
        const float2 o = g_cs[((size_t)bh * CH + c) * NB + n];
        ax = o.x; ay = o.y;
    }
    const size_t base = ((size_t)bh * SS + (size_t)c * CLEN) * NB;

    float stc, sts;
    sincosf(6.2831853071795864f * (float)n / 64.f, &sts, &stc);

    float2 w  = make_float2(0.f, 0.f), qc = make_float2(0.f, 0.f);
    if (n < NB) { w = g_w[base + n]; qc = g_qc[base + n]; }

    for (int sl = 0; sl < CLEN; sl++) {
        float2 wn = make_float2(0.f, 0.f), qn = make_float2(0.f, 0.f);
        if (n < NB && sl + 1 < CLEN) {
            wn = g_w [base + (size_t)(sl + 1) * NB + n];
            qn = g_qc[base + (size_t)(sl + 1) * NB + n];
        }
        if (n < NB) {
            ax += w.x; ay += w.y;
            of[n] = make_float2(ax * qc.x - ay * qc.y,
                                ax * qc.y + ay * qc.x);
        }
        __syncthreads();

        const float f0   = of[0].x;
        const float f32v = of[32].x;
        float cr = stc, ci = sts;
        float sum = 0.f;
#pragma unroll
        for (int j = 1; j < 32; j++) {
            sum = fmaf(of[j].x, cr, sum);
            sum = fmaf(-of[j].y, ci, sum);
            const float ncr = cr * stc - ci * sts;
            const float nci = cr * sts + ci * stc;
            cr = ncr; ci = nci;
        }
        const int s = c * CLEN + sl;
        const float outv = (f0 + ((n & 1) ? -f32v : f32v) + 2.f * sum) * (1.f / 64.f);
        out[(size_t)(b * SS + s) * DD + h * HD + n] = outv;
        __syncthreads();

        w = wn; qc = qn;
    }
}

// ---------------------------------------------------------------------------
extern "C" void kernel_launch(void* const* d_in, const int* in_sizes, int n_in,
                              void* d_out, int out_size)
{
    const float* x  = (const float*)d_in[0];
    const float* Wq = (const float*)d_in[1];
    const float* bq = (const float*)d_in[2];
    const float* Wk = (const float*)d_in[3];
    const float* bk = (const float*)d_in[4];
    const float* Wv = (const float*)d_in[5];
    const float* bv = (const float*)d_in[6];
    float* out = (float*)d_out;

    cudaFuncSetAttribute(mma_gemm_kernel,
                         cudaFuncAttributeMaxDynamicSharedMemorySize, DSMEM_BYTES);

    convert_x_kernel<<<4096, 256>>>(x);
    convert_w_kernel<<<dim3(32, 32, 3), dim3(32, 8)>>>(Wq, Wk, Wv);

    mma_gemm_kernel<<<dim3(DD / 128, MM / 128, 3), 256, DSMEM_BYTES>>>(bq, bk, bv);

    freq_kernel<<<NROW / 2, 128>>>();

    chunk_sum_kernel<<<dim3(BB * HH, CH), 64>>>();
    chunk_scan_kernel<<<BB * HH, 64>>>();
    scan_idft_kernel<<<dim3(BB * HH, CH), 64>>>(out);
}

// round 4
// speedup vs baseline: 2.6623x; 1.4147x over previous
#include <cuda_runtime.h>
#include <cuda_bf16.h>
#include <math.h>
#include <stdint.h>

#define BB 8
#define SS 2048
#define HH 16
#define HD 64
#define DD 1024
#define MM (BB*SS)          /* 16384 rows */
#define NB 33               /* rfft bins for length-64 */
#define CH 16               /* scan chunks per sequence */
#define CLEN (SS/CH)        /* 128 steps per chunk */

#define KC 32               /* K-chunk per SMEM stage */
#define NKT (DD/KC)         /* 32 stages */
#define STAGE_BYTES 32768   /* A 16KB + B 16KB (hi|lo packed in 128B rows) */
#define NSTAGE 3
#define DSMEM_BYTES (NSTAGE*STAGE_BYTES + 128)

// ---------------- scratch (static device memory; no allocs) ----------------
__device__ float  g_qkv[3][(size_t)MM*DD];                 // q,k,v spectra (packed rdft)
__device__ float2 g_w  [(size_t)BB*HH*SS*NB];              // bind spectra
__device__ float2 g_qc [(size_t)BB*HH*SS*NB];              // conj(q_hat)
__device__ float2 g_cs [(size_t)BB*HH*CH*NB];              // chunk partial sums
__device__ __nv_bfloat16 g_xhi[(size_t)MM*DD];             // X split hi
__device__ __nv_bfloat16 g_xlo[(size_t)MM*DD];             // X split lo
__device__ __nv_bfloat16 g_wthi[3][(size_t)DD*DD];         // (W*F)^T split hi [N][K]
__device__ __nv_bfloat16 g_wtlo[3][(size_t)DD*DD];         // (W*F)^T split lo [N][K]
__device__ float g_bias[3][DD];                            // transformed bias

// ------------------------------ PTX helpers -------------------------------
__device__ __forceinline__ uint32_t smem_u32(const void* p) {
    uint32_t a;
    asm("{ .reg .u64 t; cvta.to.shared.u64 t, %1; cvt.u32.u64 %0, t; }"
        : "=r"(a) : "l"(p));
    return a;
}
__device__ __forceinline__ void cp16(uint32_t dst, const void* src) {
    asm volatile("cp.async.cg.shared.global [%0], [%1], 16;"
                 :: "r"(dst), "l"(src) : "memory");
}
__device__ __forceinline__ void cp_commit() {
    asm volatile("cp.async.commit_group;" ::: "memory");
}
__device__ __forceinline__ void cp_wait2() {
    asm volatile("cp.async.wait_group 2;" ::: "memory");
}
__device__ __forceinline__ void ldsm4(uint32_t& r0, uint32_t& r1, uint32_t& r2,
                                      uint32_t& r3, uint32_t addr) {
    asm volatile("ldmatrix.sync.aligned.m8n8.x4.shared.b16 {%0,%1,%2,%3}, [%4];"
                 : "=r"(r0), "=r"(r1), "=r"(r2), "=r"(r3) : "r"(addr));
}
__device__ __forceinline__ void mma_bf16(float* c, const uint32_t* a, const uint32_t* b) {
    asm volatile("mma.sync.aligned.m16n8k16.row.col.f32.bf16.bf16.f32 "
                 "{%0,%1,%2,%3},{%4,%5,%6,%7},{%8,%9},{%0,%1,%2,%3};"
                 : "+f"(c[0]), "+f"(c[1]), "+f"(c[2]), "+f"(c[3])
                 : "r"(a[0]), "r"(a[1]), "r"(a[2]), "r"(a[3]),
                   "r"(b[0]), "r"(b[1]));
}

// ---------------------------------------------------------------------------
// Convert X (fp32) -> bf16 hi/lo pair
// ---------------------------------------------------------------------------
__global__ __launch_bounds__(256)
void convert_x_kernel(const float* __restrict__ X)
{
    const size_t total = (size_t)MM * DD / 4;
    for (size_t i = blockIdx.x * 256 + threadIdx.x; i < total; i += (size_t)gridDim.x * 256) {
        float4 f = ((const float4*)X)[i];
        __nv_bfloat16 h0 = __float2bfloat16(f.x);
        __nv_bfloat16 h1 = __float2bfloat16(f.y);
        __nv_bfloat16 h2 = __float2bfloat16(f.z);
        __nv_bfloat16 h3 = __float2bfloat16(f.w);
        __nv_bfloat16 l0 = __float2bfloat16(f.x - __bfloat162float(h0));
        __nv_bfloat16 l1 = __float2bfloat16(f.y - __bfloat162float(h1));
        __nv_bfloat16 l2 = __float2bfloat16(f.z - __bfloat162float(h2));
        __nv_bfloat16 l3 = __float2bfloat16(f.w - __bfloat162float(h3));
        ((__nv_bfloat162*)g_xhi)[i * 2 + 0] = __nv_bfloat162(h0, h1);
        ((__nv_bfloat162*)g_xhi)[i * 2 + 1] = __nv_bfloat162(h2, h3);
        ((__nv_bfloat162*)g_xlo)[i * 2 + 0] = __nv_bfloat162(l0, l1);
        ((__nv_bfloat162*)g_xlo)[i * 2 + 1] = __nv_bfloat162(l2, l3);
    }
}

// ---------------------------------------------------------------------------
// W' = W * F (per-head packed real-DFT), output transposed [N][K], split hi/lo.
// Packing per head: col p in [0,32] = re(bin p); p in [33,63] = im(bin p-32).
// Forward DFT: re = sum x_t cos(2pi j t/64), im = -sum x_t sin(2pi j t/64).
// grid: (K/64, HH, 3), block 256.
// ---------------------------------------------------------------------------
__global__ __launch_bounds__(256)
void wtransform_kernel(const float* __restrict__ Wq,
                       const float* __restrict__ Wk,
                       const float* __restrict__ Wv)
{
    __shared__ float sW[64][65];   // [t][kk]
    __shared__ float sB[64][65];   // [p][t]
    const int which = blockIdx.z;
    const int h = blockIdx.y;
    const int k0 = blockIdx.x * 64;
    const float* W = (which == 0) ? Wq : (which == 1) ? Wk : Wv;
    const int tid = threadIdx.x;

    for (int e = tid; e < 4096; e += 256) {
        const int p = e >> 6, t = e & 63;
        const int bin = (p <= 32) ? p : (p - 32);
        float sn, cs;
        sincosf(6.2831853071795864f * (float)((bin * t) & 63) / 64.f, &sn, &cs);
        sB[p][t] = (p <= 32) ? cs : -sn;
    }
#pragma unroll
    for (int pass = 0; pass < 16; pass++) {
        const int kk = pass * 4 + (tid >> 6);
        const int t = tid & 63;
        sW[t][kk] = W[(size_t)(k0 + kk) * DD + h * 64 + t];
    }
    __syncthreads();

    for (int e = tid; e < 4096; e += 256) {
        const int p = e >> 6, kk = e & 63;
        float acc = 0.f;
#pragma unroll 16
        for (int t = 0; t < 64; t++)
            acc = fmaf(sB[p][t], sW[t][kk], acc);
        const __nv_bfloat16 hi = __float2bfloat16(acc);
        const __nv_bfloat16 lo = __float2bfloat16(acc - __bfloat162float(hi));
        const size_t o = (size_t)(h * 64 + p) * DD + k0 + kk;
        g_wthi[which][o] = hi;
        g_wtlo[which][o] = lo;
    }
}

// ---------------------------------------------------------------------------
// Transformed bias: b' = b * F (same packing). grid 3, block 256.
// ---------------------------------------------------------------------------
__global__ __launch_bounds__(256)
void btransform_kernel(const float* __restrict__ bq,
                       const float* __restrict__ bk,
                       const float* __restrict__ bv)
{
    const int which = blockIdx.x;
    const float* b = (which == 0) ? bq : (which == 1) ? bk : bv;
    const int tid = threadIdx.x;
#pragma unroll
    for (int i = 0; i < 4; i++) {
        const int n = tid + i * 256;
        const int h = n >> 6, p = n & 63;
        const int bin = (p <= 32) ? p : (p - 32);
        float acc = 0.f;
        for (int t = 0; t < 64; t++) {
            float sn, cs;
            sincosf(6.2831853071795864f * (float)((bin * t) & 63) / 64.f, &sn, &cs);
            acc = fmaf(b[h * 64 + t], (p <= 32) ? cs : -sn, acc);
        }
        g_bias[which][n] = acc;
    }
}

// ---------------------------------------------------------------------------
// Split-bf16 HMMA GEMM: spectra = X @ (W F) + b'. CTA 128x128, 8 warps,
// mma m16n8k16 bf16, 3-stage cp.async ring, SW128 XOR swizzle.
// ---------------------------------------------------------------------------
__device__ __forceinline__ void copy_stage(uint32_t sA, uint32_t sB, int which,
                                           int rowB, int colB, int kt, int tid)
{
#pragma unroll
    for (int i = 0; i < 4; i++) {
        const int id = tid + i * 256;
        const int r = id >> 3, c = id & 7;
        const __nv_bfloat16* g = (c < 4) ? g_xhi : g_xlo;
        const void* src = g + (size_t)(rowB + r) * DD + kt * KC + (c & 3) * 8;
        cp16(sA + r * 128 + ((c ^ (r & 7)) << 4), src);
    }
#pragma unroll
    for (int i = 0; i < 4; i++) {
        const int id = tid + i * 256;
        const int r = id >> 3, c = id & 7;
        const __nv_bfloat16* g = (c < 4) ? g_wthi[which] : g_wtlo[which];
        const void* src = g + (size_t)(colB + r) * DD + kt * KC + (c & 3) * 8;
        cp16(sB + r * 128 + ((c ^ (r & 7)) << 4), src);
    }
}

__global__ __launch_bounds__(256)
void mma_gemm_kernel()
{
    extern __shared__ __align__(16) char dsm[];
    const int tid = threadIdx.x;
    const int wid = tid >> 5, lane = tid & 31;
    const int wm = wid & 1, wn = wid >> 1;
    const int which = blockIdx.z;
    const int rowB = blockIdx.y * 128;
    const int colB = blockIdx.x * 128;

    uint32_t sbase = smem_u32(dsm);
    sbase = (sbase + 127u) & ~127u;

    float C[4][4][4];
#pragma unroll
    for (int mt = 0; mt < 4; mt++)
#pragma unroll
        for (int nt = 0; nt < 4; nt++)
#pragma unroll
            for (int j = 0; j < 4; j++) C[mt][nt][j] = 0.f;

    copy_stage(sbase, sbase + 16384, which, rowB, colB, 0, tid);
    cp_commit();
    copy_stage(sbase + STAGE_BYTES, sbase + STAGE_BYTES + 16384, which, rowB, colB, 1, tid);
    cp_commit();

    for (int kt = 0; kt < NKT; kt++) {
        if (kt + 2 < NKT) {
            const uint32_t dA = sbase + ((kt + 2) % NSTAGE) * STAGE_BYTES;
            copy_stage(dA, dA + 16384, which, rowB, colB, kt + 2, tid);
        }
        cp_commit();
        cp_wait2();
        __syncthreads();
        const uint32_t sA = sbase + (kt % NSTAGE) * STAGE_BYTES;
        const uint32_t sB = sA + 16384;

#pragma unroll
        for (int ks = 0; ks < 2; ks++) {
            uint32_t a[2][4][4];
            uint32_t b[2][4][2];
#pragma unroll
            for (int h = 0; h < 2; h++)
#pragma unroll
                for (int mt = 0; mt < 4; mt++) {
                    const int row = wm * 64 + mt * 16 + (lane & 15);
                    const int c = 2 * ks + (lane >> 4) + h * 4;
                    ldsm4(a[h][mt][0], a[h][mt][1], a[h][mt][2], a[h][mt][3],
                          sA + row * 128 + ((c ^ (row & 7)) << 4));
                }
#pragma unroll
            for (int h = 0; h < 2; h++)
#pragma unroll
                for (int p = 0; p < 2; p++) {
                    const int row = wn * 32 + p * 16 + ((lane >> 4) << 3) + (lane & 7);
                    const int c = 2 * ks + ((lane >> 3) & 1) + h * 4;
                    ldsm4(b[h][2 * p][0], b[h][2 * p][1],
                          b[h][2 * p + 1][0], b[h][2 * p + 1][1],
                          sB + row * 128 + ((c ^ (row & 7)) << 4));
                }
#pragma unroll
            for (int mt = 0; mt < 4; mt++)
#pragma unroll
                for (int nt = 0; nt < 4; nt++) {
                    mma_bf16(C[mt][nt], a[0][mt], b[0][nt]);  // hi*hi
                    mma_bf16(C[mt][nt], a[0][mt], b[1][nt]);  // hi*lo
                    mma_bf16(C[mt][nt], a[1][mt], b[0][nt]);  // lo*hi
                }
        }
        __syncthreads();
    }

    // Epilogue: fp32 stores + transformed bias
    float* Cg = &g_qkv[which][0];
    const float* bias = g_bias[which];
    const int rw = rowB + wm * 64;
    const int cw = colB + wn * 32;
#pragma unroll
    for (int mt = 0; mt < 4; mt++) {
#pragma unroll
        for (int nt = 0; nt < 4; nt++) {
            const int r0 = rw + mt * 16 + (lane >> 2);
            const int col = cw + nt * 8 + (lane & 3) * 2;
            const float bx = bias[col], by = bias[col + 1];
            float2 o0 = make_float2(C[mt][nt][0] + bx, C[mt][nt][1] + by);
            float2 o1 = make_float2(C[mt][nt][2] + bx, C[mt][nt][3] + by);
            *(float2*)&Cg[(size_t)r0 * DD + col]       = o0;
            *(float2*)&Cg[(size_t)(r0 + 8) * DD + col] = o1;
        }
    }
}

// ---------------------------------------------------------------------------
// Post: normalize spectra to unit magnitude, w = k_hat*v_hat, qc = conj(q_hat).
// One block per row m=(b,s); packed layout cols: [re 0..32 | im 1..31] per head.
// ---------------------------------------------------------------------------
__global__ __launch_bounds__(256)
void post_kernel()
{
    __shared__ float sq[DD], sk[DD], sv[DD];
    const int m = blockIdx.x;
    const int tid = threadIdx.x;
    const float4* Q = (const float4*)&g_qkv[0][(size_t)m * DD];
    const float4* K = (const float4*)&g_qkv[1][(size_t)m * DD];
    const float4* V = (const float4*)&g_qkv[2][(size_t)m * DD];
    ((float4*)sq)[tid] = Q[tid];
    ((float4*)sk)[tid] = K[tid];
    ((float4*)sv)[tid] = V[tid];
    __syncthreads();

    const int b = m >> 11, s = m & (SS - 1);
    for (int it = tid; it < HH * NB; it += 256) {
        const int h = it / NB;
        const int j = it - h * NB;
        const int base = h * 64;
        const bool realbin = (j == 0) | (j == 32);
        float qr = sq[base + j], qi = realbin ? 0.f : sq[base + 32 + j];
        float kr = sk[base + j], ki = realbin ? 0.f : sk[base + 32 + j];
        float vr = sv[base + j], vi = realbin ? 0.f : sv[base + 32 + j];
        const float iq = 1.f / (sqrtf(qr * qr + qi * qi) + 1e-8f);
        const float ik = 1.f / (sqrtf(kr * kr + ki * ki) + 1e-8f);
        const float iv = 1.f / (sqrtf(vr * vr + vi * vi) + 1e-8f);
        qr *= iq; qi *= iq;
        kr *= ik; ki *= ik;
        vr *= iv; vi *= iv;
        const size_t idx = ((size_t)(b * HH + h) * SS + s) * NB + j;
        g_w[idx]  = make_float2(kr * vr - ki * vi, kr * vi + ki * vr);
        g_qc[idx] = make_float2(qr, -qi);
    }
}

// ---------------------------------------------------------------------------
__global__ __launch_bounds__(64)
void chunk_sum_kernel()
{
    const int bh = blockIdx.x;
    const int c  = blockIdx.y;
    const int j  = threadIdx.x;
    if (j >= NB) return;

    size_t base = ((size_t)bh * SS + (size_t)c * CLEN) * NB + j;
    float sx = 0.f, sy = 0.f;
#pragma unroll 4
    for (int s = 0; s < CLEN; s++) {
        const float2 w = g_w[base + (size_t)s * NB];
        sx += w.x; sy += w.y;
    }
    g_cs[((size_t)bh * CH + c) * NB + j] = make_float2(sx, sy);
}

__global__ __launch_bounds__(64)
void chunk_scan_kernel()
{
    const int bh = blockIdx.x;
    const int j  = threadIdx.x;
    if (j >= NB) return;

    float rx = 0.f, ry = 0.f;
#pragma unroll
    for (int c = 0; c < CH; c++) {
        const size_t idx = ((size_t)bh * CH + c) * NB + j;
        const float2 t = g_cs[idx];
        g_cs[idx] = make_float2(rx, ry);
        rx += t.x; ry += t.y;
    }
}

__global__ __launch_bounds__(64)
void scan_idft_kernel(float* __restrict__ out)
{
    __shared__ float2 of[NB];
    const int bh = blockIdx.x;
    const int c  = blockIdx.y;
    const int n  = threadIdx.x;
    const int b  = bh >> 4;
    const int h  = bh & 15;

    float ax = 0.f, ay = 0.f;
    if (n < NB) {
        const float2 o = g_cs[((size_t)bh * CH + c) * NB + n];
        ax = o.x; ay = o.y;
    }
    const size_t base = ((size_t)bh * SS + (size_t)c * CLEN) * NB;

    float stc, sts;
    sincosf(6.2831853071795864f * (float)n / 64.f, &sts, &stc);

    float2 w  = make_float2(0.f, 0.f), qc = make_float2(0.f, 0.f);
    if (n < NB) { w = g_w[base + n]; qc = g_qc[base + n]; }

    for (int sl = 0; sl < CLEN; sl++) {
        float2 wn = make_float2(0.f, 0.f), qn = make_float2(0.f, 0.f);
        if (n < NB && sl + 1 < CLEN) {
            wn = g_w [base + (size_t)(sl + 1) * NB + n];
            qn = g_qc[base + (size_t)(sl + 1) * NB + n];
        }
        if (n < NB) {
            ax += w.x; ay += w.y;
            of[n] = make_float2(ax * qc.x - ay * qc.y,
                                ax * qc.y + ay * qc.x);
        }
        __syncthreads();

        const float f0   = of[0].x;
        const float f32v = of[32].x;
        float cr = stc, ci = sts;
        float sum = 0.f;
#pragma unroll
        for (int j = 1; j < 32; j++) {
            sum = fmaf(of[j].x, cr, sum);
            sum = fmaf(-of[j].y, ci, sum);
            const float ncr = cr * stc - ci * sts;
            const float nci = cr * sts + ci * stc;
            cr = ncr; ci = nci;
        }
        const int s = c * CLEN + sl;
        const float outv = (f0 + ((n & 1) ? -f32v : f32v) + 2.f * sum) * (1.f / 64.f);
        out[(size_t)(b * SS + s) * DD + h * HD + n] = outv;
        __syncthreads();

        w = wn; qc = qn;
    }
}

// ---------------------------------------------------------------------------
extern "C" void kernel_launch(void* const* d_in, const int* in_sizes, int n_in,
                              void* d_out, int out_size)
{
    const float* x  = (const float*)d_in[0];
    const float* Wq = (const float*)d_in[1];
    const float* bq = (const float*)d_in[2];
    const float* Wk = (const float*)d_in[3];
    const float* bk = (const float*)d_in[4];
    const float* Wv = (const float*)d_in[5];
    const float* bv = (const float*)d_in[6];
    float* out = (float*)d_out;

    cudaFuncSetAttribute(mma_gemm_kernel,
                         cudaFuncAttributeMaxDynamicSharedMemorySize, DSMEM_BYTES);

    convert_x_kernel<<<4096, 256>>>(x);
    wtransform_kernel<<<dim3(DD / 64, HH, 3), 256>>>(Wq, Wk, Wv);
    btransform_kernel<<<3, 256>>>(bq, bk, bv);

    mma_gemm_kernel<<<dim3(DD / 128, MM / 128, 3), 256, DSMEM_BYTES>>>();

    post_kernel<<<MM, 256>>>();

    chunk_sum_kernel<<<dim3(BB * HH, CH), 64>>>();
    chunk_scan_kernel<<<BB * HH, 64>>>();
    scan_idft_kernel<<<dim3(BB * HH, CH), 64>>>(out);
}